// round 4
// baseline (speedup 1.0000x reference)
#include <cuda_runtime.h>
#include <math.h>

// ---------------- problem dims ----------------
#define B_   512
#define T_   256
#define H_   1024
#define C_   128

// ---------------- GEMM tiling ----------------
#define BM   128          // m tile (batch rows)
#define BN   128          // n tile (output cols)
#define BK   32           // k chunk
#define BMp  132          // padded smem stride (bank-conflict + 16B align)
#define KS   4            // K splits
#define KPS  (H_/KS)      // 256 k per split
#define NCH  (KPS/BK)     // 8 chunks
#define TM   8            // per-thread m
#define TN   8            // per-thread n
#define NTHR 256          // (BM/TM)*(BN/TN)

// ---------------- device scratch (no runtime allocation allowed) ----------------
__device__ float g_h[2][B_ * H_];          // ping-pong hidden state  (4 MB)
__device__ float g_part[KS][B_ * H_];      // split-K partials, recurrent (8 MB)
__device__ float g_parto[KS][B_ * C_];     // split-K partials, head (1 MB)

// ---------------- packed fp32x2 helpers ----------------
__device__ __forceinline__ void ffma2(unsigned long long& d,
                                      unsigned long long a,
                                      unsigned long long b) {
    asm("fma.rn.f32x2 %0, %1, %2, %0;" : "+l"(d) : "l"(a), "l"(b));
}
__device__ __forceinline__ unsigned long long dup2(float w) {
    unsigned long long r;
    asm("mov.b64 %0, {%1, %1};" : "=l"(r) : "f"(w));
    return r;
}

// =====================================================================
// Split-K partial GEMM:  part[ks][m][n] = sum_{k in split ks} A[m][k]*W[n][k]
// A: [512][1024] row-major.  W: [N][1024] row-major.  N = 1024 or 128.
// grid = (N/BN, 512/BM, KS), block = 256, dynamic smem.
// =====================================================================
__global__ void __launch_bounds__(NTHR, 1)
gemm_part_kernel(const float* __restrict__ A,
                 const float* __restrict__ W,
                 float* __restrict__ part,
                 int N)
{
    extern __shared__ float smem[];
    float (*Hs)[BK][BMp] = reinterpret_cast<float (*)[BK][BMp]>(smem);
    float (*Ws)[BK][BMp] = reinterpret_cast<float (*)[BK][BMp]>(smem + 2 * BK * BMp);

    const int tid = threadIdx.x;
    const int bn  = blockIdx.x;
    const int bm  = blockIdx.y;
    const int ks  = blockIdx.z;
    const int k0  = ks * KPS;

    // ---- global-load mapping: 32 rows x 32 k per pass, 4 passes ----
    const int lr = tid >> 3;            // 0..31 row-in-pass
    const int lk = (tid & 7) << 2;      // 0,4,...,28

    const float* Ag = A + (size_t)(bm * BM + lr) * H_ + k0 + lk;
    const float* Wg = W + (size_t)(bn * BN + lr) * H_ + k0 + lk;

    // ---- compute mapping ----
    const int tm = (tid & 15) * TM;     // 0..120
    const int tn = (tid >> 4) * TN;     // 0..120

    unsigned long long acc[4][8];       // f32x2 accumulators: (m-pair) x (n)
#pragma unroll
    for (int i = 0; i < 4; i++)
#pragma unroll
        for (int j = 0; j < 8; j++) acc[i][j] = 0ull;

    float4 ra[4], rb[4];                // LDG staging (double buffer in regs)

    auto LDG = [&](int ch) {
        const float* a = Ag + ch * BK;
        const float* w = Wg + ch * BK;
#pragma unroll
        for (int p = 0; p < 4; p++) {
            ra[p] = *reinterpret_cast<const float4*>(a + (size_t)p * 32 * H_);
            rb[p] = *reinterpret_cast<const float4*>(w + (size_t)p * 32 * H_);
        }
    };
    auto STS = [&](int buf) {
#pragma unroll
        for (int p = 0; p < 4; p++) {
            const float* va = reinterpret_cast<const float*>(&ra[p]);
            const float* vb = reinterpret_cast<const float*>(&rb[p]);
            const int m = p * 32 + lr;
#pragma unroll
            for (int q = 0; q < 4; q++) {
                Hs[buf][lk + q][m] = va[q];   // transposed [k][m]
                Ws[buf][lk + q][m] = vb[q];   // transposed [k][n]
            }
        }
    };
    auto COMPUTE = [&](int buf) {
#pragma unroll 4
        for (int kk = 0; kk < BK; kk++) {
            ulonglong2 hA = *reinterpret_cast<const ulonglong2*>(&Hs[buf][kk][tm]);
            ulonglong2 hB = *reinterpret_cast<const ulonglong2*>(&Hs[buf][kk][tm + 4]);
            float4 wa = *reinterpret_cast<const float4*>(&Ws[buf][kk][tn]);
            float4 wb = *reinterpret_cast<const float4*>(&Ws[buf][kk][tn + 4]);
            unsigned long long h[4] = { hA.x, hA.y, hB.x, hB.y };
            unsigned long long w[8] = { dup2(wa.x), dup2(wa.y), dup2(wa.z), dup2(wa.w),
                                        dup2(wb.x), dup2(wb.y), dup2(wb.z), dup2(wb.w) };
#pragma unroll
            for (int i = 0; i < 4; i++)
#pragma unroll
                for (int j = 0; j < 8; j++) ffma2(acc[i][j], h[i], w[j]);
        }
    };

    // ---- mainloop: double-buffered smem, reg-staged prefetch ----
    LDG(0);
    STS(0);
    LDG(1);
    __syncthreads();
#pragma unroll 1
    for (int ch = 0; ch < NCH; ch++) {
        const int buf = ch & 1;
        if (ch + 1 < NCH) STS(buf ^ 1);   // store chunk ch+1
        if (ch + 2 < NCH) LDG(ch + 2);    // prefetch chunk ch+2
        COMPUTE(buf);
        __syncthreads();
    }

    // ---- epilogue: unpack f32x2 pairs -> partial buffer ----
    float* P = part + (size_t)ks * B_ * N + (size_t)(bm * BM) * N + bn * BN;
#pragma unroll
    for (int i = 0; i < 4; i++) {
        const int r0 = tm + 2 * i;        // f32x2 lo = row r0, hi = row r0+1
        float2 f[8];
#pragma unroll
        for (int j = 0; j < 8; j++) f[j] = *reinterpret_cast<float2*>(&acc[i][j]);
        float4 a0 = make_float4(f[0].x, f[1].x, f[2].x, f[3].x);
        float4 a1 = make_float4(f[4].x, f[5].x, f[6].x, f[7].x);
        float4 b0 = make_float4(f[0].y, f[1].y, f[2].y, f[3].y);
        float4 b1 = make_float4(f[4].y, f[5].y, f[6].y, f[7].y);
        *reinterpret_cast<float4*>(P + (size_t)r0 * N + tn)           = a0;
        *reinterpret_cast<float4*>(P + (size_t)r0 * N + tn + 4)       = a1;
        *reinterpret_cast<float4*>(P + (size_t)(r0 + 1) * N + tn)     = b0;
        *reinterpret_cast<float4*>(P + (size_t)(r0 + 1) * N + tn + 4) = b1;
    }
}

// =====================================================================
// combine_h: h_out = tanh( sum_ks part + x[:,t]*W_hx^T + b_h )
// 131072 threads, float4 each.
// =====================================================================
__global__ void combine_h(const float* __restrict__ part,
                          const float* __restrict__ x,
                          const float* __restrict__ whx,
                          const float* __restrict__ bh,
                          float* __restrict__ hout,
                          int t, int usepart)
{
    const int idx = blockIdx.x * blockDim.x + threadIdx.x;   // 512*1024/4
    const int b = idx >> 8;
    const int j = (idx & 255) << 2;

    const float xv = x[(size_t)b * T_ + t];
    const float4 w  = *reinterpret_cast<const float4*>(whx + j);
    const float4 bb = *reinterpret_cast<const float4*>(bh + j);

    float4 s;
    s.x = fmaf(xv, w.x, bb.x);
    s.y = fmaf(xv, w.y, bb.y);
    s.z = fmaf(xv, w.z, bb.z);
    s.w = fmaf(xv, w.w, bb.w);

    if (usepart) {
        const size_t off = (size_t)b * H_ + j;
#pragma unroll
        for (int z = 0; z < KS; z++) {
            float4 p = *reinterpret_cast<const float4*>(part + (size_t)z * B_ * H_ + off);
            s.x += p.x; s.y += p.y; s.z += p.z; s.w += p.w;
        }
    }
    s.x = tanhf(s.x);
    s.y = tanhf(s.y);
    s.z = tanhf(s.z);
    s.w = tanhf(s.w);
    *reinterpret_cast<float4*>(hout + (size_t)b * H_ + j) = s;
}

// =====================================================================
// combine_o: out = sum_ks parto + b_p
// =====================================================================
__global__ void combine_o(const float* __restrict__ parto,
                          const float* __restrict__ bp,
                          float* __restrict__ out)
{
    const int idx = blockIdx.x * blockDim.x + threadIdx.x;   // 512*128/4
    const int b = idx >> 5;
    const int c = (idx & 31) << 2;
    float4 s = *reinterpret_cast<const float4*>(bp + c);
    const size_t off = (size_t)b * C_ + c;
#pragma unroll
    for (int z = 0; z < KS; z++) {
        float4 p = *reinterpret_cast<const float4*>(parto + (size_t)z * B_ * C_ + off);
        s.x += p.x; s.y += p.y; s.z += p.z; s.w += p.w;
    }
    *reinterpret_cast<float4*>(out + off) = s;
}

// =====================================================================
// launch
// =====================================================================
extern "C" void kernel_launch(void* const* d_in, const int* in_sizes, int n_in,
                              void* d_out, int out_size)
{
    const float* x   = (const float*)d_in[0];   // [512,256]
    const float* whx = (const float*)d_in[1];   // [1024,1]
    const float* whh = (const float*)d_in[2];   // [1024,1024]
    const float* bh  = (const float*)d_in[3];   // [1024]
    const float* wph = (const float*)d_in[4];   // [128,1024]
    const float* bp  = (const float*)d_in[5];   // [128]
    float* out = (float*)d_out;                 // [512,128]

    float *hbuf, *part, *parto;
    cudaGetSymbolAddress((void**)&hbuf,  g_h);
    cudaGetSymbolAddress((void**)&part,  g_part);
    cudaGetSymbolAddress((void**)&parto, g_parto);
    float* h0 = hbuf;
    float* h1 = hbuf + (size_t)B_ * H_;

    const size_t smemBytes = (size_t)2 * BK * BMp * sizeof(float) * 2;  // ~67.6 KB
    cudaFuncSetAttribute(gemm_part_kernel,
                         cudaFuncAttributeMaxDynamicSharedMemorySize, (int)smemBytes);

    // step 0: h = tanh(x_0 * W_hx^T + b_h)  (h_prev = 0)
    combine_h<<<512, 256>>>(part, x, whx, bh, h0, 0, 0);

    // steps 1..255
    for (int t = 1; t < T_; t++) {
        const float* hin = (t & 1) ? h0 : h1;
        float*       hov = (t & 1) ? h1 : h0;
        gemm_part_kernel<<<dim3(H_ / BN, B_ / BM, KS), NTHR, smemBytes>>>(hin, whh, part, H_);
        combine_h<<<512, 256>>>(part, x, whx, bh, hov, t, 1);
    }

    // output head: out = h_last @ W_ph^T + b_p   (t=255 wrote h1)
    gemm_part_kernel<<<dim3(1, B_ / BM, KS), NTHR, smemBytes>>>(h1, wph, parto, C_);
    combine_o<<<(B_ * C_ / 4) / 256, 256>>>(parto, bp, out);
}

// round 6
// speedup vs baseline: 1.7617x; 1.7617x over previous
#include <cuda_runtime.h>
#include <cuda_bf16.h>
#include <math.h>
#include <stdint.h>

// ---------------- problem dims ----------------
#define B_   512
#define T_   256
#define H_   1024
#define C_   128

// ---------------- step-kernel tiling ----------------
#define BM 64
#define BN 64
#define BK 32
#define KP 40                      // padded k-stride (elems) -> conflict-free ldmatrix
#define NCH (H_ / BK)              // 32 chunks
#define ARR_BYTES (64 * KP * 2)    // 5120 per operand array
#define STG_BYTES (4 * ARR_BYTES)  // 20480 per stage
#define NSTAGE 3
#define STEP_SMEM (NSTAGE * STG_BYTES)   // 61440

// ---------------- device scratch (no runtime allocation allowed) ----------------
__device__ float          g_h[B_ * H_];
__device__ __nv_bfloat16  g_whi[H_ * H_], g_wlo[H_ * H_];
__device__ __nv_bfloat16  g_ahi[2][B_ * H_], g_alo[2][B_ * H_];
__device__ float          g_parto[4][B_ * C_];

// ---------------- base-ISA PTX helpers (compute_103-safe) ----------------
__device__ __forceinline__ uint32_t smem_u32(const void* p) {
    uint32_t a;
    asm("{ .reg .u64 t; cvta.to.shared.u64 t, %1; cvt.u32.u64 %0, t; }"
        : "=r"(a) : "l"(p));
    return a;
}
#define CP16(d, s) \
    asm volatile("cp.async.cg.shared.global [%0], [%1], 16;" :: "r"(d), "l"(s))
#define CPCOMMIT() asm volatile("cp.async.commit_group;" ::: "memory")
#define CPWAIT1()  asm volatile("cp.async.wait_group 1;" ::: "memory")
#define CPWAIT0()  asm volatile("cp.async.wait_group 0;" ::: "memory")

#define LDSM4(r, addr) \
    asm volatile("ldmatrix.sync.aligned.m8n8.x4.shared.b16 {%0,%1,%2,%3}, [%4];" \
        : "=r"((r)[0]), "=r"((r)[1]), "=r"((r)[2]), "=r"((r)[3]) : "r"(addr))

#define MMA16816(c, a, b0, b1) \
    asm volatile("mma.sync.aligned.m16n8k16.row.col.f32.bf16.bf16.f32 " \
        "{%0,%1,%2,%3}, {%4,%5,%6,%7}, {%8,%9}, {%0,%1,%2,%3};" \
        : "+f"((c)[0]), "+f"((c)[1]), "+f"((c)[2]), "+f"((c)[3]) \
        : "r"((a)[0]), "r"((a)[1]), "r"((a)[2]), "r"((a)[3]), "r"(b0), "r"(b1))

// =====================================================================
// per-step kernel: acc = Ahi*Whi^T + Ahi*Wlo^T + Alo*Whi^T (all bf16 MMA),
// fused epilogue h = tanh(acc + x_t*W_hx + b_h), writes next hi/lo splits.
// grid (16, 8) = 128 CTAs, 128 threads (4 warps, warp tile 32x32).
// =====================================================================
__global__ void __launch_bounds__(128, 1)
rnn_step(const __nv_bfloat16* __restrict__ ahi, const __nv_bfloat16* __restrict__ alo,
         const __nv_bfloat16* __restrict__ whi, const __nv_bfloat16* __restrict__ wlo,
         const float* __restrict__ x, const float* __restrict__ whx,
         const float* __restrict__ bh,
         float* __restrict__ hout,
         __nv_bfloat16* __restrict__ ahi_o, __nv_bfloat16* __restrict__ alo_o,
         int t, int last)
{
    extern __shared__ char smem[];
    const uint32_t sb = smem_u32(smem);
    const int tid  = threadIdx.x;
    const int wid  = tid >> 5;
    const int lane = tid & 31;
    const int bn   = blockIdx.x;
    const int bm   = blockIdx.y;
    const int wm   = (wid & 1) * 32;    // warp tile m origin
    const int wn   = (wid >> 1) * 32;   // warp tile n origin

    const __nv_bfloat16* srcs[4] = {
        ahi + (size_t)(bm * BM) * H_,
        alo + (size_t)(bm * BM) * H_,
        whi + (size_t)(bn * BN) * H_,
        wlo + (size_t)(bn * BN) * H_
    };

    float acc[2][4][4];
#pragma unroll
    for (int mi = 0; mi < 2; mi++)
#pragma unroll
        for (int ni = 0; ni < 4; ni++)
#pragma unroll
            for (int q = 0; q < 4; q++) acc[mi][ni][q] = 0.0f;

    auto LOAD = [&](int ch, int slot) {
        const uint32_t base = sb + slot * STG_BYTES;
        const int k0 = ch * BK;
#pragma unroll
        for (int r = 0; r < 4; r++) {
            const __nv_bfloat16* s = srcs[r];
            const uint32_t ab = base + r * ARR_BYTES;
#pragma unroll
            for (int i = 0; i < 2; i++) {
                const int u   = tid + i * 128;      // 0..255
                const int row = u >> 2;             // 0..63
                const int ko  = (u & 3) * 8;        // 0,8,16,24
                CP16(ab + (uint32_t)(row * KP + ko) * 2,
                     s + (size_t)row * H_ + k0 + ko);
            }
        }
    };

    const int tdiv8 = lane >> 3;
    const int tmod8 = lane & 7;

    auto COMPUTE = [&](int slot) {
        const uint32_t base = sb + slot * STG_BYTES;
        const uint32_t aHI = base;
        const uint32_t aLO = base + ARR_BYTES;
        const uint32_t wHI = base + 2 * ARR_BYTES;
        const uint32_t wLO = base + 3 * ARR_BYTES;
#pragma unroll
        for (int ks = 0; ks < 2; ks++) {
            uint32_t Ah[2][4], Al[2][4], Wh[2][4], Wl[2][4];
            // A fragments: tiles (m0-7,k0-7)(m8-15,k0-7)(m0-7,k8-15)(m8-15,k8-15)
#pragma unroll
            for (int mi = 0; mi < 2; mi++) {
                const int row = wm + mi * 16 + ((tdiv8 & 1) << 3) + tmod8;
                const int col = ks * 16 + ((tdiv8 >> 1) << 3);
                const uint32_t off = (uint32_t)(row * KP + col) * 2;
                LDSM4(Ah[mi], aHI + off);
                LDSM4(Al[mi], aLO + off);
            }
            // W fragments: tiles (n0-7,k0-7)(n0-7,k8-15)(n8-15,k0-7)(n8-15,k8-15)
#pragma unroll
            for (int np = 0; np < 2; np++) {
                const int row = wn + np * 16 + ((tdiv8 >> 1) << 3) + tmod8;
                const int col = ks * 16 + ((tdiv8 & 1) << 3);
                const uint32_t off = (uint32_t)(row * KP + col) * 2;
                LDSM4(Wh[np], wHI + off);
                LDSM4(Wl[np], wLO + off);
            }
            // product 0: Ahi*Whi, 1: Ahi*Wlo, 2: Alo*Whi (8 indep accs per product)
#pragma unroll
            for (int p = 0; p < 3; p++) {
                uint32_t (*A)[4] = (p == 2) ? Al : Ah;
                uint32_t (*W)[4] = (p == 1) ? Wl : Wh;
#pragma unroll
                for (int mi = 0; mi < 2; mi++)
#pragma unroll
                    for (int ni = 0; ni < 4; ni++) {
                        const int np = ni >> 1, hf = (ni & 1) * 2;
                        MMA16816(acc[mi][ni], A[mi], W[np][hf], W[np][hf + 1]);
                    }
            }
        }
    };

    // ---------------- 3-stage cp.async mainloop ----------------
    LOAD(0, 0); CPCOMMIT();
    LOAD(1, 1); CPCOMMIT();
#pragma unroll 1
    for (int c = 0; c < NCH; c++) {
        if (c < NCH - 1) { CPWAIT1(); } else { CPWAIT0(); }
        __syncthreads();
        if (c + 2 < NCH) { LOAD(c + 2, (c + 2) % NSTAGE); CPCOMMIT(); }
        COMPUTE(c % NSTAGE);
        __syncthreads();
    }

    // ---------------- fused epilogue ----------------
    const int qc = (lane & 3) * 2;
#pragma unroll
    for (int ni = 0; ni < 4; ni++) {
        const int j = bn * BN + wn + ni * 8 + qc;
        const float w0 = whx[j],     w1 = whx[j + 1];
        const float b0 = bh[j],      b1 = bh[j + 1];
#pragma unroll
        for (int mi = 0; mi < 2; mi++) {
#pragma unroll
            for (int hf = 0; hf < 2; hf++) {
                const int row = wm + mi * 16 + (lane >> 2) + hf * 8;
                const int gm  = bm * BM + row;
                const float xv = x[(size_t)gm * T_ + t];
                const float c0 = acc[mi][ni][hf * 2];
                const float c1 = acc[mi][ni][hf * 2 + 1];
                const float h0 = tanhf(fmaf(xv, w0, b0) + c0);
                const float h1 = tanhf(fmaf(xv, w1, b1) + c1);
                const size_t o = (size_t)gm * H_ + j;
                const __nv_bfloat16 h0h = __float2bfloat16(h0);
                const __nv_bfloat16 h1h = __float2bfloat16(h1);
                __nv_bfloat162 hi2; hi2.x = h0h; hi2.y = h1h;
                *reinterpret_cast<__nv_bfloat162*>(ahi_o + o) = hi2;
                __nv_bfloat162 lo2;
                lo2.x = __float2bfloat16(h0 - __bfloat162float(h0h));
                lo2.y = __float2bfloat16(h1 - __bfloat162float(h1h));
                *reinterpret_cast<__nv_bfloat162*>(alo_o + o) = lo2;
                if (last) {
                    float2 f2; f2.x = h0; f2.y = h1;
                    *reinterpret_cast<float2*>(hout + o) = f2;
                }
            }
        }
    }
}

// ================= one-time helpers =================
__global__ void split_w(const float* __restrict__ w,
                        __nv_bfloat16* __restrict__ hi, __nv_bfloat16* __restrict__ lo)
{
    const int i = (blockIdx.x * blockDim.x + threadIdx.x) * 4;
    float4 v = *reinterpret_cast<const float4*>(w + i);
    const float vv[4] = { v.x, v.y, v.z, v.w };
#pragma unroll
    for (int q = 0; q < 4; q++) {
        __nv_bfloat16 h = __float2bfloat16(vv[q]);
        hi[i + q] = h;
        lo[i + q] = __float2bfloat16(vv[q] - __bfloat162float(h));
    }
}

__global__ void init_h(const float* __restrict__ x, const float* __restrict__ whx,
                       const float* __restrict__ bh,
                       __nv_bfloat16* __restrict__ ahi, __nv_bfloat16* __restrict__ alo)
{
    const int idx = blockIdx.x * blockDim.x + threadIdx.x;  // 131072
    const int b = idx >> 8;
    const int j0 = (idx & 255) << 2;
    const float xv = x[(size_t)b * T_];      // t = 0
#pragma unroll
    for (int q = 0; q < 4; q++) {
        const int j = j0 + q;
        const float hs = tanhf(fmaf(xv, whx[j], bh[j]));
        const size_t o = (size_t)b * H_ + j;
        __nv_bfloat16 hb = __float2bfloat16(hs);
        ahi[o] = hb;
        alo[o] = __float2bfloat16(hs - __bfloat162float(hb));
    }
}

// ================= head GEMM (proven SIMT split-K, N=128) =================
#define GBM   128
#define GBK   32
#define GBMp  132
#define GKS   4
#define GKPS  (H_ / GKS)
#define GNCH  (GKPS / GBK)

__device__ __forceinline__ void ffma2(unsigned long long& d,
                                      unsigned long long a, unsigned long long b) {
    asm("fma.rn.f32x2 %0, %1, %2, %0;" : "+l"(d) : "l"(a), "l"(b));
}
__device__ __forceinline__ unsigned long long dup2(float w) {
    unsigned long long r;
    asm("mov.b64 %0, {%1, %1};" : "=l"(r) : "f"(w));
    return r;
}

__global__ void __launch_bounds__(256, 1)
gemm_part_kernel(const float* __restrict__ A, const float* __restrict__ W,
                 float* __restrict__ part, int N)
{
    extern __shared__ float fsm[];
    float (*Hs)[GBK][GBMp] = reinterpret_cast<float (*)[GBK][GBMp]>(fsm);
    float (*Ws)[GBK][GBMp] = reinterpret_cast<float (*)[GBK][GBMp]>(fsm + 2 * GBK * GBMp);

    const int tid = threadIdx.x;
    const int bn = blockIdx.x, bm = blockIdx.y, ks = blockIdx.z;
    const int k0 = ks * GKPS;
    const int lr = tid >> 3, lk = (tid & 7) << 2;
    const float* Ag = A + (size_t)(bm * GBM + lr) * H_ + k0 + lk;
    const float* Wg = W + (size_t)(bn * 128 + lr) * H_ + k0 + lk;
    const int tm = (tid & 15) * 8, tn = (tid >> 4) * 8;

    unsigned long long acc[4][8];
#pragma unroll
    for (int i = 0; i < 4; i++)
#pragma unroll
        for (int j = 0; j < 8; j++) acc[i][j] = 0ull;

    float4 ra[4], rb[4];
    auto LDG = [&](int ch) {
        const float* a = Ag + ch * GBK;
        const float* w = Wg + ch * GBK;
#pragma unroll
        for (int p = 0; p < 4; p++) {
            ra[p] = *reinterpret_cast<const float4*>(a + (size_t)p * 32 * H_);
            rb[p] = *reinterpret_cast<const float4*>(w + (size_t)p * 32 * H_);
        }
    };
    auto STS = [&](int buf) {
#pragma unroll
        for (int p = 0; p < 4; p++) {
            const float* va = reinterpret_cast<const float*>(&ra[p]);
            const float* vb = reinterpret_cast<const float*>(&rb[p]);
            const int m = p * 32 + lr;
#pragma unroll
            for (int q = 0; q < 4; q++) {
                Hs[buf][lk + q][m] = va[q];
                Ws[buf][lk + q][m] = vb[q];
            }
        }
    };
    auto COMPUTE = [&](int buf) {
#pragma unroll 4
        for (int kk = 0; kk < GBK; kk++) {
            ulonglong2 hA = *reinterpret_cast<const ulonglong2*>(&Hs[buf][kk][tm]);
            ulonglong2 hB = *reinterpret_cast<const ulonglong2*>(&Hs[buf][kk][tm + 4]);
            float4 wa = *reinterpret_cast<const float4*>(&Ws[buf][kk][tn]);
            float4 wb = *reinterpret_cast<const float4*>(&Ws[buf][kk][tn + 4]);
            unsigned long long h[4] = { hA.x, hA.y, hB.x, hB.y };
            unsigned long long w[8] = { dup2(wa.x), dup2(wa.y), dup2(wa.z), dup2(wa.w),
                                        dup2(wb.x), dup2(wb.y), dup2(wb.z), dup2(wb.w) };
#pragma unroll
            for (int i = 0; i < 4; i++)
#pragma unroll
                for (int j = 0; j < 8; j++) ffma2(acc[i][j], h[i], w[j]);
        }
    };

    LDG(0); STS(0); LDG(1);
    __syncthreads();
#pragma unroll 1
    for (int ch = 0; ch < GNCH; ch++) {
        const int buf = ch & 1;
        if (ch + 1 < GNCH) STS(buf ^ 1);
        if (ch + 2 < GNCH) LDG(ch + 2);
        COMPUTE(buf);
        __syncthreads();
    }

    float* P = part + (size_t)ks * B_ * N + (size_t)(bm * GBM) * N + bn * 128;
#pragma unroll
    for (int i = 0; i < 4; i++) {
        const int r0 = tm + 2 * i;
        float2 f[8];
#pragma unroll
        for (int j = 0; j < 8; j++) f[j] = *reinterpret_cast<float2*>(&acc[i][j]);
        *reinterpret_cast<float4*>(P + (size_t)r0 * N + tn)           = make_float4(f[0].x, f[1].x, f[2].x, f[3].x);
        *reinterpret_cast<float4*>(P + (size_t)r0 * N + tn + 4)       = make_float4(f[4].x, f[5].x, f[6].x, f[7].x);
        *reinterpret_cast<float4*>(P + (size_t)(r0 + 1) * N + tn)     = make_float4(f[0].y, f[1].y, f[2].y, f[3].y);
        *reinterpret_cast<float4*>(P + (size_t)(r0 + 1) * N + tn + 4) = make_float4(f[4].y, f[5].y, f[6].y, f[7].y);
    }
}

__global__ void combine_o(const float* __restrict__ parto,
                          const float* __restrict__ bp, float* __restrict__ out)
{
    const int idx = blockIdx.x * blockDim.x + threadIdx.x;
    const int b = idx >> 5;
    const int c = (idx & 31) << 2;
    float4 s = *reinterpret_cast<const float4*>(bp + c);
    const size_t off = (size_t)b * C_ + c;
#pragma unroll
    for (int z = 0; z < GKS; z++) {
        float4 p = *reinterpret_cast<const float4*>(parto + (size_t)z * B_ * C_ + off);
        s.x += p.x; s.y += p.y; s.z += p.z; s.w += p.w;
    }
    *reinterpret_cast<float4*>(out + off) = s;
}

// ================= launch =================
extern "C" void kernel_launch(void* const* d_in, const int* in_sizes, int n_in,
                              void* d_out, int out_size)
{
    const float* x   = (const float*)d_in[0];   // [512,256]
    const float* whx = (const float*)d_in[1];   // [1024,1]
    const float* whh = (const float*)d_in[2];   // [1024,1024]
    const float* bh  = (const float*)d_in[3];   // [1024]
    const float* wph = (const float*)d_in[4];   // [128,1024]
    const float* bp  = (const float*)d_in[5];   // [128]
    float* out = (float*)d_out;                 // [512,128]

    float *h, *parto;
    __nv_bfloat16 *wh_hi, *wh_lo, *a_hi, *a_lo;
    cudaGetSymbolAddress((void**)&h,     g_h);
    cudaGetSymbolAddress((void**)&wh_hi, g_whi);
    cudaGetSymbolAddress((void**)&wh_lo, g_wlo);
    cudaGetSymbolAddress((void**)&a_hi,  g_ahi);
    cudaGetSymbolAddress((void**)&a_lo,  g_alo);
    cudaGetSymbolAddress((void**)&parto, g_parto);

    cudaFuncSetAttribute(rnn_step, cudaFuncAttributeMaxDynamicSharedMemorySize, STEP_SMEM);
    const size_t gsmem = (size_t)2 * GBK * GBMp * sizeof(float) * 2;
    cudaFuncSetAttribute(gemm_part_kernel, cudaFuncAttributeMaxDynamicSharedMemorySize, (int)gsmem);

    // one-time: split W_hh into hi/lo bf16
    split_w<<<1024, 256>>>(whh, wh_hi, wh_lo);

    // step 0: h = tanh(x_0 * W_hx^T + b_h)
    init_h<<<512, 256>>>(x, whx, bh, a_hi, a_lo);

    // steps 1..255 on tensor cores (base-ISA mma.sync path)
    const size_t HB = (size_t)B_ * H_;
    for (int t = 1; t < T_; t++) {
        const int ib = (t - 1) & 1, ob = t & 1;
        rnn_step<<<dim3(H_ / BN, B_ / BM), 128, STEP_SMEM>>>(
            a_hi + (size_t)ib * HB, a_lo + (size_t)ib * HB,
            wh_hi, wh_lo, x, whx, bh,
            h, a_hi + (size_t)ob * HB, a_lo + (size_t)ob * HB,
            t, (t == T_ - 1) ? 1 : 0);
    }

    // head: out = h_last @ W_ph^T + b_p
    gemm_part_kernel<<<dim3(1, B_ / GBM, GKS), 256, gsmem>>>(h, wph, parto, C_);
    combine_o<<<(B_ * C_ / 4) / 256, 256>>>(parto, bp, out);
}

// round 7
// speedup vs baseline: 2.0678x; 1.1738x over previous
#include <cuda_runtime.h>
#include <cuda_bf16.h>
#include <math.h>
#include <stdint.h>

// ---------------- problem dims ----------------
#define B_   512
#define T_   256
#define H_   1024
#define C_   128

// ---------------- step-kernel tiling ----------------
#define BM 64
#define BN 64
#define BK 64
#define KP 72                      // padded k-stride (elems) -> conflict-free ldmatrix
#define NCH (H_ / BK)              // 16 chunks
#define ARR_BYTES (64 * KP * 2)    // 9216 per operand array
#define STG_BYTES (4 * ARR_BYTES)  // 36864 per stage
#define NSTAGE 4
#define STEP_SMEM (NSTAGE * STG_BYTES)   // 147456 bytes

// ---------------- device scratch (no runtime allocation allowed) ----------------
__device__ float          g_h[B_ * H_];
__device__ __nv_bfloat16  g_whi[H_ * H_], g_wlo[H_ * H_];
__device__ __nv_bfloat16  g_ahi[2][B_ * H_], g_alo[2][B_ * H_];
__device__ float          g_parto[4][B_ * C_];

// ---------------- base-ISA PTX helpers (compute_103-safe) ----------------
__device__ __forceinline__ uint32_t smem_u32(const void* p) {
    uint32_t a;
    asm("{ .reg .u64 t; cvta.to.shared.u64 t, %1; cvt.u32.u64 %0, t; }"
        : "=r"(a) : "l"(p));
    return a;
}
#define CP16(d, s) \
    asm volatile("cp.async.cg.shared.global [%0], [%1], 16;" :: "r"(d), "l"(s))
#define CPCOMMIT() asm volatile("cp.async.commit_group;" ::: "memory")
#define CPWAIT(n)  asm volatile("cp.async.wait_group %0;" :: "n"(n) : "memory")

#define LDSM4(r, addr) \
    asm volatile("ldmatrix.sync.aligned.m8n8.x4.shared.b16 {%0,%1,%2,%3}, [%4];" \
        : "=r"((r)[0]), "=r"((r)[1]), "=r"((r)[2]), "=r"((r)[3]) : "r"(addr))

#define MMA16816(c, a, b0, b1) \
    asm volatile("mma.sync.aligned.m16n8k16.row.col.f32.bf16.bf16.f32 " \
        "{%0,%1,%2,%3}, {%4,%5,%6,%7}, {%8,%9}, {%0,%1,%2,%3};" \
        : "+f"((c)[0]), "+f"((c)[1]), "+f"((c)[2]), "+f"((c)[3]) \
        : "r"((a)[0]), "r"((a)[1]), "r"((a)[2]), "r"((a)[3]), "r"(b0), "r"(b1))

// =====================================================================
// per-step kernel: acc = Ahi*Whi^T + Ahi*Wlo^T + Alo*Whi^T (all bf16 MMA),
// fused epilogue h = tanh(acc + x_t*W_hx + b_h), writes next hi/lo splits.
// grid (16, 8) = 128 CTAs, 256 threads (8 warps, warp tile 32x16 -> 2/SMSP).
// 4-stage cp.async pipeline, ONE __syncthreads per 64-k chunk.
// =====================================================================
__global__ void __launch_bounds__(256, 1)
rnn_step(const __nv_bfloat16* __restrict__ ahi, const __nv_bfloat16* __restrict__ alo,
         const __nv_bfloat16* __restrict__ whi, const __nv_bfloat16* __restrict__ wlo,
         const float* __restrict__ x, const float* __restrict__ whx,
         const float* __restrict__ bh,
         float* __restrict__ hout,
         __nv_bfloat16* __restrict__ ahi_o, __nv_bfloat16* __restrict__ alo_o,
         int t, int last)
{
    extern __shared__ char smem[];
    const uint32_t sb = smem_u32(smem);
    const int tid  = threadIdx.x;
    const int wid  = tid >> 5;
    const int lane = tid & 31;
    const int bn   = blockIdx.x;
    const int bm   = blockIdx.y;
    const int wm   = (wid & 1) * 32;    // warp tile m origin (2 m-warps)
    const int wn   = (wid >> 1) * 16;   // warp tile n origin (4 n-warps)

    const __nv_bfloat16* srcs[4] = {
        ahi + (size_t)(bm * BM) * H_,
        alo + (size_t)(bm * BM) * H_,
        whi + (size_t)(bn * BN) * H_,
        wlo + (size_t)(bn * BN) * H_
    };

    float acc[2][2][4];                 // [mi][ni][quad]
#pragma unroll
    for (int mi = 0; mi < 2; mi++)
#pragma unroll
        for (int ni = 0; ni < 2; ni++)
#pragma unroll
            for (int q = 0; q < 4; q++) acc[mi][ni][q] = 0.0f;

    auto LOAD = [&](int ch, int slot) {
        const uint32_t base = sb + slot * STG_BYTES;
        const int k0 = ch * BK;
#pragma unroll
        for (int r = 0; r < 4; r++) {
            const __nv_bfloat16* s = srcs[r];
            const uint32_t ab = base + r * ARR_BYTES;
#pragma unroll
            for (int i = 0; i < 2; i++) {
                const int u   = tid + i * 256;      // 0..511
                const int row = u >> 3;             // 0..63
                const int ko  = (u & 7) * 8;        // 0..56
                CP16(ab + (uint32_t)(row * KP + ko) * 2,
                     s + (size_t)row * H_ + k0 + ko);
            }
        }
    };

    const int tdiv8 = lane >> 3;
    const int tmod8 = lane & 7;

    auto COMPUTE = [&](int slot) {
        const uint32_t base = sb + slot * STG_BYTES;
        const uint32_t aHI = base;
        const uint32_t aLO = base + ARR_BYTES;
        const uint32_t wHI = base + 2 * ARR_BYTES;
        const uint32_t wLO = base + 3 * ARR_BYTES;
#pragma unroll
        for (int ks = 0; ks < 4; ks++) {
            uint32_t Ah[2][4], Al[2][4], Wh[4], Wl[4];
            // A fragments: LDSM4 tiles (m0-7,k0-7)(m8-15,k0-7)(m0-7,k8-15)(m8-15,k8-15)
#pragma unroll
            for (int mi = 0; mi < 2; mi++) {
                const int row = wm + mi * 16 + ((tdiv8 & 1) << 3) + tmod8;
                const int col = ks * 16 + ((tdiv8 >> 1) << 3);
                const uint32_t off = (uint32_t)(row * KP + col) * 2;
                LDSM4(Ah[mi], aHI + off);
                LDSM4(Al[mi], aLO + off);
            }
            // W fragments: LDSM4 tiles (n0-7,k0-7)(n0-7,k8-15)(n8-15,k0-7)(n8-15,k8-15)
            {
                const int row = wn + ((tdiv8 >> 1) << 3) + tmod8;
                const int col = ks * 16 + ((tdiv8 & 1) << 3);
                const uint32_t off = (uint32_t)(row * KP + col) * 2;
                LDSM4(Wh, wHI + off);
                LDSM4(Wl, wLO + off);
            }
            // products: Ahi*Whi, Ahi*Wlo, Alo*Whi (4 indep accs each)
#pragma unroll
            for (int p = 0; p < 3; p++) {
                uint32_t (*A)[4] = (p == 2) ? Al : Ah;
                uint32_t* W      = (p == 1) ? Wl : Wh;
#pragma unroll
                for (int mi = 0; mi < 2; mi++)
#pragma unroll
                    for (int ni = 0; ni < 2; ni++)
                        MMA16816(acc[mi][ni], A[mi], W[ni * 2], W[ni * 2 + 1]);
            }
        }
    };

    // ---------------- 4-stage cp.async mainloop, one barrier/chunk ----------------
    LOAD(0, 0); CPCOMMIT();
    LOAD(1, 1); CPCOMMIT();
    LOAD(2, 2); CPCOMMIT();
#pragma unroll 1
    for (int c = 0; c < NCH; c++) {
        if (c < NCH - 2)       { CPWAIT(2); }   // group c complete
        else if (c == NCH - 2) { CPWAIT(1); }
        else                   { CPWAIT(0); }
        __syncthreads();                         // all warps done with slot (c+3)&3's old data
        if (c + 3 < NCH) { LOAD(c + 3, (c + 3) & 3); CPCOMMIT(); }
        COMPUTE(c & 3);
    }

    // ---------------- fused epilogue ----------------
    const int qc = (lane & 3) * 2;
#pragma unroll
    for (int ni = 0; ni < 2; ni++) {
        const int j = bn * BN + wn + ni * 8 + qc;
        const float w0 = whx[j],     w1 = whx[j + 1];
        const float b0 = bh[j],      b1 = bh[j + 1];
#pragma unroll
        for (int mi = 0; mi < 2; mi++) {
#pragma unroll
            for (int hf = 0; hf < 2; hf++) {
                const int row = wm + mi * 16 + (lane >> 2) + hf * 8;
                const int gm  = bm * BM + row;
                const float xv = x[(size_t)gm * T_ + t];
                const float c0 = acc[mi][ni][hf * 2];
                const float c1 = acc[mi][ni][hf * 2 + 1];
                const float h0 = tanhf(fmaf(xv, w0, b0) + c0);
                const float h1 = tanhf(fmaf(xv, w1, b1) + c1);
                const size_t o = (size_t)gm * H_ + j;
                const __nv_bfloat16 h0h = __float2bfloat16(h0);
                const __nv_bfloat16 h1h = __float2bfloat16(h1);
                __nv_bfloat162 hi2; hi2.x = h0h; hi2.y = h1h;
                *reinterpret_cast<__nv_bfloat162*>(ahi_o + o) = hi2;
                __nv_bfloat162 lo2;
                lo2.x = __float2bfloat16(h0 - __bfloat162float(h0h));
                lo2.y = __float2bfloat16(h1 - __bfloat162float(h1h));
                *reinterpret_cast<__nv_bfloat162*>(alo_o + o) = lo2;
                if (last) {
                    float2 f2; f2.x = h0; f2.y = h1;
                    *reinterpret_cast<float2*>(hout + o) = f2;
                }
            }
        }
    }
}

// ================= one-time helpers =================
__global__ void split_w(const float* __restrict__ w,
                        __nv_bfloat16* __restrict__ hi, __nv_bfloat16* __restrict__ lo)
{
    const int i = (blockIdx.x * blockDim.x + threadIdx.x) * 4;
    float4 v = *reinterpret_cast<const float4*>(w + i);
    const float vv[4] = { v.x, v.y, v.z, v.w };
#pragma unroll
    for (int q = 0; q < 4; q++) {
        __nv_bfloat16 h = __float2bfloat16(vv[q]);
        hi[i + q] = h;
        lo[i + q] = __float2bfloat16(vv[q] - __bfloat162float(h));
    }
}

__global__ void init_h(const float* __restrict__ x, const float* __restrict__ whx,
                       const float* __restrict__ bh,
                       __nv_bfloat16* __restrict__ ahi, __nv_bfloat16* __restrict__ alo)
{
    const int idx = blockIdx.x * blockDim.x + threadIdx.x;  // 131072
    const int b = idx >> 8;
    const int j0 = (idx & 255) << 2;
    const float xv = x[(size_t)b * T_];      // t = 0
#pragma unroll
    for (int q = 0; q < 4; q++) {
        const int j = j0 + q;
        const float hs = tanhf(fmaf(xv, whx[j], bh[j]));
        const size_t o = (size_t)b * H_ + j;
        __nv_bfloat16 hb = __float2bfloat16(hs);
        ahi[o] = hb;
        alo[o] = __float2bfloat16(hs - __bfloat162float(hb));
    }
}

// ================= head GEMM (proven SIMT split-K, N=128) =================
#define GBM   128
#define GBK   32
#define GBMp  132
#define GKS   4
#define GKPS  (H_ / GKS)
#define GNCH  (GKPS / GBK)

__device__ __forceinline__ void ffma2(unsigned long long& d,
                                      unsigned long long a, unsigned long long b) {
    asm("fma.rn.f32x2 %0, %1, %2, %0;" : "+l"(d) : "l"(a), "l"(b));
}
__device__ __forceinline__ unsigned long long dup2(float w) {
    unsigned long long r;
    asm("mov.b64 %0, {%1, %1};" : "=l"(r) : "f"(w));
    return r;
}

__global__ void __launch_bounds__(256, 1)
gemm_part_kernel(const float* __restrict__ A, const float* __restrict__ W,
                 float* __restrict__ part, int N)
{
    extern __shared__ float fsm[];
    float (*Hs)[GBK][GBMp] = reinterpret_cast<float (*)[GBK][GBMp]>(fsm);
    float (*Ws)[GBK][GBMp] = reinterpret_cast<float (*)[GBK][GBMp]>(fsm + 2 * GBK * GBMp);

    const int tid = threadIdx.x;
    const int bn = blockIdx.x, bm = blockIdx.y, ks = blockIdx.z;
    const int k0 = ks * GKPS;
    const int lr = tid >> 3, lk = (tid & 7) << 2;
    const float* Ag = A + (size_t)(bm * GBM + lr) * H_ + k0 + lk;
    const float* Wg = W + (size_t)(bn * 128 + lr) * H_ + k0 + lk;
    const int tm = (tid & 15) * 8, tn = (tid >> 4) * 8;

    unsigned long long acc[4][8];
#pragma unroll
    for (int i = 0; i < 4; i++)
#pragma unroll
        for (int j = 0; j < 8; j++) acc[i][j] = 0ull;

    float4 ra[4], rb[4];
    auto LDG = [&](int ch) {
        const float* a = Ag + ch * GBK;
        const float* w = Wg + ch * GBK;
#pragma unroll
        for (int p = 0; p < 4; p++) {
            ra[p] = *reinterpret_cast<const float4*>(a + (size_t)p * 32 * H_);
            rb[p] = *reinterpret_cast<const float4*>(w + (size_t)p * 32 * H_);
        }
    };
    auto STS = [&](int buf) {
#pragma unroll
        for (int p = 0; p < 4; p++) {
            const float* va = reinterpret_cast<const float*>(&ra[p]);
            const float* vb = reinterpret_cast<const float*>(&rb[p]);
            const int m = p * 32 + lr;
#pragma unroll
            for (int q = 0; q < 4; q++) {
                Hs[buf][lk + q][m] = va[q];
                Ws[buf][lk + q][m] = vb[q];
            }
        }
    };
    auto COMPUTE = [&](int buf) {
#pragma unroll 4
        for (int kk = 0; kk < GBK; kk++) {
            ulonglong2 hA = *reinterpret_cast<const ulonglong2*>(&Hs[buf][kk][tm]);
            ulonglong2 hB = *reinterpret_cast<const ulonglong2*>(&Hs[buf][kk][tm + 4]);
            float4 wa = *reinterpret_cast<const float4*>(&Ws[buf][kk][tn]);
            float4 wb = *reinterpret_cast<const float4*>(&Ws[buf][kk][tn + 4]);
            unsigned long long h[4] = { hA.x, hA.y, hB.x, hB.y };
            unsigned long long w[8] = { dup2(wa.x), dup2(wa.y), dup2(wa.z), dup2(wa.w),
                                        dup2(wb.x), dup2(wb.y), dup2(wb.z), dup2(wb.w) };
#pragma unroll
            for (int i = 0; i < 4; i++)
#pragma unroll
                for (int j = 0; j < 8; j++) ffma2(acc[i][j], h[i], w[j]);
        }
    };

    LDG(0); STS(0); LDG(1);
    __syncthreads();
#pragma unroll 1
    for (int ch = 0; ch < GNCH; ch++) {
        const int buf = ch & 1;
        if (ch + 1 < GNCH) STS(buf ^ 1);
        if (ch + 2 < GNCH) LDG(ch + 2);
        COMPUTE(buf);
        __syncthreads();
    }

    float* P = part + (size_t)ks * B_ * N + (size_t)(bm * GBM) * N + bn * 128;
#pragma unroll
    for (int i = 0; i < 4; i++) {
        const int r0 = tm + 2 * i;
        float2 f[8];
#pragma unroll
        for (int j = 0; j < 8; j++) f[j] = *reinterpret_cast<float2*>(&acc[i][j]);
        *reinterpret_cast<float4*>(P + (size_t)r0 * N + tn)           = make_float4(f[0].x, f[1].x, f[2].x, f[3].x);
        *reinterpret_cast<float4*>(P + (size_t)r0 * N + tn + 4)       = make_float4(f[4].x, f[5].x, f[6].x, f[7].x);
        *reinterpret_cast<float4*>(P + (size_t)(r0 + 1) * N + tn)     = make_float4(f[0].y, f[1].y, f[2].y, f[3].y);
        *reinterpret_cast<float4*>(P + (size_t)(r0 + 1) * N + tn + 4) = make_float4(f[4].y, f[5].y, f[6].y, f[7].y);
    }
}

__global__ void combine_o(const float* __restrict__ parto,
                          const float* __restrict__ bp, float* __restrict__ out)
{
    const int idx = blockIdx.x * blockDim.x + threadIdx.x;
    const int b = idx >> 5;
    const int c = (idx & 31) << 2;
    float4 s = *reinterpret_cast<const float4*>(bp + c);
    const size_t off = (size_t)b * C_ + c;
#pragma unroll
    for (int z = 0; z < GKS; z++) {
        float4 p = *reinterpret_cast<const float4*>(parto + (size_t)z * B_ * C_ + off);
        s.x += p.x; s.y += p.y; s.z += p.z; s.w += p.w;
    }
    *reinterpret_cast<float4*>(out + off) = s;
}

// ================= launch =================
extern "C" void kernel_launch(void* const* d_in, const int* in_sizes, int n_in,
                              void* d_out, int out_size)
{
    const float* x   = (const float*)d_in[0];   // [512,256]
    const float* whx = (const float*)d_in[1];   // [1024,1]
    const float* whh = (const float*)d_in[2];   // [1024,1024]
    const float* bh  = (const float*)d_in[3];   // [1024]
    const float* wph = (const float*)d_in[4];   // [128,1024]
    const float* bp  = (const float*)d_in[5];   // [128]
    float* out = (float*)d_out;                 // [512,128]

    float *h, *parto;
    __nv_bfloat16 *wh_hi, *wh_lo, *a_hi, *a_lo;
    cudaGetSymbolAddress((void**)&h,     g_h);
    cudaGetSymbolAddress((void**)&wh_hi, g_whi);
    cudaGetSymbolAddress((void**)&wh_lo, g_wlo);
    cudaGetSymbolAddress((void**)&a_hi,  g_ahi);
    cudaGetSymbolAddress((void**)&a_lo,  g_alo);
    cudaGetSymbolAddress((void**)&parto, g_parto);

    cudaFuncSetAttribute(rnn_step, cudaFuncAttributeMaxDynamicSharedMemorySize, STEP_SMEM);
    const size_t gsmem = (size_t)2 * GBK * GBMp * sizeof(float) * 2;
    cudaFuncSetAttribute(gemm_part_kernel, cudaFuncAttributeMaxDynamicSharedMemorySize, (int)gsmem);

    // one-time: split W_hh into hi/lo bf16
    split_w<<<1024, 256>>>(whh, wh_hi, wh_lo);

    // step 0: h = tanh(x_0 * W_hx^T + b_h)
    init_h<<<512, 256>>>(x, whx, bh, a_hi, a_lo);

    // steps 1..255 on tensor cores (base-ISA mma.sync path)
    const size_t HB = (size_t)B_ * H_;
    for (int t = 1; t < T_; t++) {
        const int ib = (t - 1) & 1, ob = t & 1;
        rnn_step<<<dim3(H_ / BN, B_ / BM), 256, STEP_SMEM>>>(
            a_hi + (size_t)ib * HB, a_lo + (size_t)ib * HB,
            wh_hi, wh_lo, x, whx, bh,
            h, a_hi + (size_t)ob * HB, a_lo + (size_t)ob * HB,
            t, (t == T_ - 1) ? 1 : 0);
    }

    // head: out = h_last @ W_ph^T + b_p
    gemm_part_kernel<<<dim3(1, B_ / GBM, GKS), 256, gsmem>>>(h, wph, parto, C_);
    combine_o<<<(B_ * C_ / 4) / 256, 256>>>(parto, bp, out);
}